// round 1
// baseline (speedup 1.0000x reference)
#include <cuda_runtime.h>
#include <cuda_bf16.h>

// Problem constants
#define Dz 48
#define Hy 256
#define Wx 256
#define DM 48
#define HM 128
#define WM 128
#define PH 4

// One thread per output voxel (p, d, h, w); computes both channels (float2).
// Fuses: trilinear 128->256 upsample of the 3-channel flow (exact 2-tap/axis
// closed form of jax.image.resize half-pixel triangle kernel), flow scaling
// [1,2,2], and zeros-padded trilinear grid sample of the 2-channel image.
__global__ void __launch_bounds__(256)
mvf_warp_kernel(const float* __restrict__ image,
                const float* __restrict__ mvf,
                float* __restrict__ out)
{
    int idx = blockIdx.x * blockDim.x + threadIdx.x;
    // idx = ((p*Dz + d)*Hy + h)*Wx + w
    int w = idx & (Wx - 1);
    int h = (idx >> 8) & (Hy - 1);
    int t = idx >> 16;           // t = p*Dz + d, max 191
    int p = t / Dz;
    int d = t - p * Dz;
    if (p >= PH) return;

    // ---- Upsample taps (exact jax.image.resize 'trilinear', scale (1,2,2)) ----
    // even out index 2k:   0.25*in[k-1] + 0.75*in[k]   (clamp at 0)
    // odd  out index 2k+1: 0.75*in[k]   + 0.25*in[k+1] (clamp at HM-1/WM-1)
    int kh = h >> 1, kw = w >> 1;
    int y0, y1, x0, x1;
    float wy0, wy1, wx0, wx1;
    if (h & 1) { y0 = kh; y1 = min(kh + 1, HM - 1); wy0 = 0.75f; wy1 = 0.25f; }
    else       { y0 = max(kh - 1, 0); y1 = kh;      wy0 = 0.25f; wy1 = 0.75f; }
    if (w & 1) { x0 = kw; x1 = min(kw + 1, WM - 1); wx0 = 0.75f; wx1 = 0.25f; }
    else       { x0 = max(kw - 1, 0); x1 = kw;      wx0 = 0.25f; wx1 = 0.75f; }

    const int plane = HM * WM;
    float fl[3];
#pragma unroll
    for (int c = 0; c < 3; c++) {
        const float* m = mvf + (((size_t)p * 3 + c) * DM + d) * plane;
        float r0 = wx0 * __ldg(m + y0 * WM + x0) + wx1 * __ldg(m + y0 * WM + x1);
        float r1 = wx0 * __ldg(m + y1 * WM + x0) + wx1 * __ldg(m + y1 * WM + x1);
        fl[c] = wy0 * r0 + wy1 * r1;
    }

    // coords = grid + flow * [1, 2, 2]
    float z = (float)d + fl[0];
    float y = (float)h + 2.0f * fl[1];
    float x = (float)w + 2.0f * fl[2];

    // ---- Zeros-padded trilinear sample ----
    float zf = floorf(z), yf = floorf(y), xf = floorf(x);
    int zb = (int)zf, yb = (int)yf, xb = (int)xf;
    float wz = z - zf, wy = y - yf, wx = x - xf;

    int   zi[2] = { zb, zb + 1 };
    int   yi[2] = { yb, yb + 1 };
    int   xi[2] = { xb, xb + 1 };
    float wzs[2] = { 1.0f - wz, wz };
    float wys[2] = { 1.0f - wy, wy };
    float wxs[2] = { 1.0f - wx, wx };
#pragma unroll
    for (int a = 0; a < 2; a++) {
        if (zi[a] < 0 || zi[a] >= Dz) { wzs[a] = 0.0f; zi[a] = 0; }
        if (yi[a] < 0 || yi[a] >= Hy) { wys[a] = 0.0f; yi[a] = 0; }
        if (xi[a] < 0 || xi[a] >= Wx) { wxs[a] = 0.0f; xi[a] = 0; }
    }

    const float2* __restrict__ img2 = (const float2*)image;
    float accx = 0.0f, accy = 0.0f;
#pragma unroll
    for (int az = 0; az < 2; az++) {
        int zoff = zi[az] * Hy;
#pragma unroll
        for (int ay = 0; ay < 2; ay++) {
            int yoff = (zoff + yi[ay]) * Wx;
            float wzy = wzs[az] * wys[ay];
#pragma unroll
            for (int ax = 0; ax < 2; ax++) {
                float wgt = wzy * wxs[ax];
                float2 v = __ldg(&img2[yoff + xi[ax]]);
                accx = fmaf(wgt, v.x, accx);
                accy = fmaf(wgt, v.y, accy);
            }
        }
    }

    // out[0, p+1, d, h, w, :] — phase 0 is the memcpy'd identity slab
    float2* o2 = (float2*)out;
    size_t slab = (size_t)Dz * Hy * Wx;                 // voxels per phase
    o2[(size_t)(p + 1) * slab + (size_t)((d * Hy + h) * Wx + w)]
        = make_float2(accx, accy);
}

extern "C" void kernel_launch(void* const* d_in, const int* in_sizes, int n_in,
                              void* d_out, int out_size)
{
    const float* image = (const float*)d_in[0];   // [1,1,48,256,256,2] f32
    const float* mvf   = (const float*)d_in[1];   // [1,4,3,48,128,128] f32
    float* out = (float*)d_out;                   // [1,5,48,256,256,2] f32

    // Phase 0: identity copy of the input image (25 MB D2D).
    size_t img_bytes = (size_t)Dz * Hy * Wx * 2 * sizeof(float);
    cudaMemcpyAsync(out, image, img_bytes, cudaMemcpyDeviceToDevice);

    // Phases 1..4: fused upsample + warp.
    int total = PH * Dz * Hy * Wx;                // 12,582,912 threads
    int threads = 256;
    int blocks = (total + threads - 1) / threads; // 49152
    mvf_warp_kernel<<<blocks, threads>>>(image, mvf, out);
}

// round 2
// speedup vs baseline: 1.0423x; 1.0423x over previous
#include <cuda_runtime.h>
#include <cuda_bf16.h>

#define Dz 48
#define Hy 256
#define Wx 256
#define DM 48
#define HM 128
#define WM 128
#define PH 4

// One thread per 2x2 output tile (h in {2kh,2kh+1}, w in {2kw,2kw+1}).
// The 4 outputs share one 3x3 mvf tap stencil per channel (27 loads vs 48),
// and write two float4 stores. Fuses the exact closed form of
// jax.image.resize trilinear (1,2,2) upsample + flow scale [1,2,2] +
// zeros-padded trilinear grid sample of the 2-channel image.
__global__ void __launch_bounds__(256)
mvf_warp_kernel(const float* __restrict__ image,
                const float* __restrict__ mvf,
                float* __restrict__ out)
{
    int idx = blockIdx.x * blockDim.x + threadIdx.x;
    // idx = ((p*Dz + d)*128 + kh)*128 + kw
    int kw = idx & (WM - 1);
    int kh = (idx >> 7) & (HM - 1);
    int t  = idx >> 14;            // p*Dz + d, 0..191
    int p  = t / Dz;
    int d  = t - p * Dz;

    // Clamped 3x3 stencil indices in coarse flow space.
    int rm = max(kh - 1, 0), r0 = kh, rp = min(kh + 1, HM - 1);
    int cm = max(kw - 1, 0), c0 = kw, cp = min(kw + 1, WM - 1);

    // Upsampled flow for the 4 outputs, per channel.
    // even output (2k):   0.25*in[k-1] + 0.75*in[k]
    // odd  output (2k+1): 0.75*in[k]   + 0.25*in[k+1]
    float fl[3][4];   // [channel][hh*2+ww]
    const int plane = HM * WM;
#pragma unroll
    for (int c = 0; c < 3; c++) {
        const float* m = mvf + (((size_t)p * 3 + c) * DM + d) * plane;
        const float* Rm = m + rm * WM;
        const float* R0 = m + r0 * WM;
        const float* Rp = m + rp * WM;
        float m00 = __ldg(Rm + cm), m01 = __ldg(Rm + c0), m02 = __ldg(Rm + cp);
        float m10 = __ldg(R0 + cm), m11 = __ldg(R0 + c0), m12 = __ldg(R0 + cp);
        float m20 = __ldg(Rp + cm), m21 = __ldg(Rp + c0), m22 = __ldg(Rp + cp);
        // column combine per row
        float e0 = 0.25f * m00 + 0.75f * m01;   // row rm, even w
        float o0 = 0.75f * m01 + 0.25f * m02;   // row rm, odd  w
        float e1 = 0.25f * m10 + 0.75f * m11;
        float o1 = 0.75f * m11 + 0.25f * m12;
        float e2 = 0.25f * m20 + 0.75f * m21;
        float o2 = 0.75f * m21 + 0.25f * m22;
        // row combine
        fl[c][0] = 0.25f * e0 + 0.75f * e1;     // h even, w even
        fl[c][1] = 0.25f * o0 + 0.75f * o1;     // h even, w odd
        fl[c][2] = 0.75f * e1 + 0.25f * e2;     // h odd,  w even
        fl[c][3] = 0.75f * o1 + 0.25f * o2;     // h odd,  w odd
    }

    const float2* __restrict__ img2 = (const float2*)image;
    int h0 = kh << 1, w0 = kw << 1;
    float2 res[4];

#pragma unroll
    for (int q = 0; q < 4; q++) {
        int hh = q >> 1, ww = q & 1;
        float z = (float)d +          fl[0][q];
        float y = (float)(h0 + hh) + 2.0f * fl[1][q];
        float x = (float)(w0 + ww) + 2.0f * fl[2][q];

        float zf = floorf(z), yf = floorf(y), xf = floorf(x);
        int zb = (int)zf, yb = (int)yf, xb = (int)xf;
        float wz = z - zf, wy = y - yf, wx = x - xf;

        int   zi[2] = { zb, zb + 1 };
        int   yi[2] = { yb, yb + 1 };
        int   xi[2] = { xb, xb + 1 };
        float wzs[2] = { 1.0f - wz, wz };
        float wys[2] = { 1.0f - wy, wy };
        float wxs[2] = { 1.0f - wx, wx };
#pragma unroll
        for (int a = 0; a < 2; a++) {
            if (zi[a] < 0 || zi[a] >= Dz) { wzs[a] = 0.0f; zi[a] = 0; }
            if (yi[a] < 0 || yi[a] >= Hy) { wys[a] = 0.0f; yi[a] = 0; }
            if (xi[a] < 0 || xi[a] >= Wx) { wxs[a] = 0.0f; xi[a] = 0; }
        }

        float ax = 0.0f, ay = 0.0f;
#pragma unroll
        for (int az = 0; az < 2; az++) {
            int zoff = zi[az] * Hy;
#pragma unroll
            for (int ayi = 0; ayi < 2; ayi++) {
                int yoff = (zoff + yi[ayi]) * Wx;
                float wzy = wzs[az] * wys[ayi];
#pragma unroll
                for (int axi = 0; axi < 2; axi++) {
                    float wgt = wzy * wxs[axi];
                    float2 v = __ldg(&img2[yoff + xi[axi]]);
                    ax = fmaf(wgt, v.x, ax);
                    ay = fmaf(wgt, v.y, ay);
                }
            }
        }
        res[q] = make_float2(ax, ay);
    }

    // Two 16B stores: rows h0 and h0+1, columns w0..w0+1.
    float2* o2 = (float2*)out;
    size_t slab = (size_t)Dz * Hy * Wx;
    size_t base = (size_t)(p + 1) * slab + (size_t)(d * Hy) * Wx + (size_t)w0;
    float4* s0 = (float4*)&o2[base + (size_t)h0 * Wx];
    float4* s1 = (float4*)&o2[base + (size_t)(h0 + 1) * Wx];
    *s0 = make_float4(res[0].x, res[0].y, res[1].x, res[1].y);
    *s1 = make_float4(res[2].x, res[2].y, res[3].x, res[3].y);
}

extern "C" void kernel_launch(void* const* d_in, const int* in_sizes, int n_in,
                              void* d_out, int out_size)
{
    const float* image = (const float*)d_in[0];   // [1,1,48,256,256,2] f32
    const float* mvf   = (const float*)d_in[1];   // [1,4,3,48,128,128] f32
    float* out = (float*)d_out;                   // [1,5,48,256,256,2] f32

    // Phase 0: identity copy of the input image (25 MB D2D).
    size_t img_bytes = (size_t)Dz * Hy * Wx * 2 * sizeof(float);
    cudaMemcpyAsync(out, image, img_bytes, cudaMemcpyDeviceToDevice);

    // Phases 1..4: fused upsample + warp, one thread per 2x2 output tile.
    int total = PH * Dz * (HM) * (WM);            // 3,145,728 threads
    int threads = 256;
    int blocks = total / threads;                 // 12288
    mvf_warp_kernel<<<blocks, threads>>>(image, mvf, out);
}